// round 4
// baseline (speedup 1.0000x reference)
#include <cuda_runtime.h>
#include <cstdint>

// Conv2d direct: input (64,8,256,256) f32 NCHW, filter (8,8,3,3) OIHW,
// VALID, stride 1 -> out (64,8,254,254) f32.
//
// R3: column-pair f32x2, but packs amortized per-channel (not per-r):
//  - xa/xb pairs loaded directly as aligned LDS.64 (zero ALU), only the
//    straddling xm pair needs a pack: 5 packs/channel vs 36 in R2.
//  - weights {w,w}-duplicated in SMEM, fetched 4 pairs at a time via LDS.128.
//  - JPT=3 rows/thread so acc+cache fits <128 regs (no spills, 2 CTAs/SM).

#define CONV_N 64
#define CONV_C 8
#define CONV_H 256
#define CONV_W 256
#define CONV_M 8
#define CONV_P 254
#define CONV_Q 254

#define TILE_W 64      // 32 threads x 2 cols
#define TILE_H 24      // 8 ty x 3 rows
#define JPT 3
#define CPB 4

typedef unsigned long long ull;

__global__ __launch_bounds__(256, 2)
void Im2Col_Conv2d_6854767804820_kernel(const float* __restrict__ in,
                                        const float* __restrict__ filt,
                                        float* __restrict__ out)
{
    __shared__ float sIn[CPB][TILE_H + 2][66];                 // 4*26*66*4 = 27456 B
    __shared__ __align__(16) float2 sWd[CONV_C * 9][CONV_M];   // 72*8*8    =  4608 B

    const int tx  = threadIdx.x;            // 0..31  (column pair)
    const int ty  = threadIdx.y;            // 0..7   (row group)
    const int tid = ty * 32 + tx;

    const int col0 = blockIdx.x * TILE_W;   // 0,64,128,192
    const int row0 = blockIdx.y * TILE_H;   // 0..240
    const int n    = blockIdx.z;

    // ---- filter, duplicated: sWd[rem][m] = {w, w};  rem=(c*3+r)*3+s
    for (int i = tid; i < CONV_M * CONV_C * 9; i += 256) {
        int m   = i / 72;
        int rem = i % 72;
        float w = filt[m * 72 + rem];
        sWd[rem][m] = make_float2(w, w);
    }

    const float* inN = in + (size_t)n * CONV_C * CONV_H * CONV_W;

    ull acc[JPT][CONV_M];
#pragma unroll
    for (int j = 0; j < JPT; j++)
#pragma unroll
        for (int m = 0; m < CONV_M; m++) acc[j][m] = 0ull;

    const int rbase = ty * JPT;
    const int q2    = 2 * tx;

    float* sInFlat = &sIn[0][0][0];

    for (int cb = 0; cb < CONV_C / CPB; cb++) {
        __syncthreads();

        // ---- stage CPB channels of the halo tile: 4*26*66 = 6864 floats.
        // OOB rows/cols are clamped (their values only feed never-stored outputs).
#pragma unroll
        for (int k = 0; k < 27; k++) {
            int i = tid + k * 256;
            if (i < CPB * (TILE_H + 2) * 66) {
                int col = i % 66;
                int t   = i / 66;
                int row = t % (TILE_H + 2);
                int cl  = t / (TILE_H + 2);
                int gr = row0 + row; if (gr > CONV_H - 1) gr = CONV_H - 1;
                int gc = col0 + col; if (gc > CONV_W - 1) gc = CONV_W - 1;
                sInFlat[i] = inN[((size_t)(cb * CPB + cl) * CONV_H + gr) * CONV_W + gc];
            }
        }
        __syncthreads();

#pragma unroll
        for (int cl = 0; cl < CPB; cl++) {
            const int c = cb * CPB + cl;

            // cache the 5 input rows this thread needs, as packed pairs:
            // xa[t] = {x[q], x[q+1]}  (aligned LDS.64)
            // xb[t] = {x[q+2], x[q+3]} (aligned LDS.64)
            // xm[t] = {x[q+1], x[q+2]} (one pack from xa.hi, xb.lo)
            ull xa[JPT + 2], xb[JPT + 2], xm[JPT + 2];
#pragma unroll
            for (int t = 0; t < JPT + 2; t++) {
                const float* p = &sIn[cl][rbase + t][q2];
                xa[t] = *reinterpret_cast<const ull*>(p);
                xb[t] = *reinterpret_cast<const ull*>(p + 2);
                asm("{\n\t"
                    ".reg .f32 a,b,cc,d;\n\t"
                    "mov.b64 {a,b}, %1;\n\t"
                    "mov.b64 {cc,d}, %2;\n\t"
                    "mov.b64 %0, {b,cc};\n\t"
                    "}"
                    : "=l"(xm[t]) : "l"(xa[t]), "l"(xb[t]));
            }

#pragma unroll
            for (int r = 0; r < 3; r++) {
#pragma unroll
                for (int s = 0; s < 3; s++) {
                    // 8 duplicated weight pairs for this (c,r,s): 4x LDS.128
                    ull w2[CONV_M];
                    const ulonglong2* wrow =
                        reinterpret_cast<const ulonglong2*>(&sWd[(c * 3 + r) * 3 + s][0]);
#pragma unroll
                    for (int h = 0; h < 4; h++) {
                        ulonglong2 v = wrow[h];
                        w2[2 * h]     = v.x;
                        w2[2 * h + 1] = v.y;
                    }

#pragma unroll
                    for (int j = 0; j < JPT; j++) {
                        ull xv = (s == 0) ? xa[j + r] : (s == 1) ? xm[j + r] : xb[j + r];
#pragma unroll
                        for (int m = 0; m < CONV_M; m++) {
                            asm("fma.rn.f32x2 %0, %1, %2, %0;"
                                : "+l"(acc[j][m])
                                : "l"(xv), "l"(w2[m]));
                        }
                    }
                }
            }
        }
    }

    // ---- store: out[n][m][orow][ocol], column pair via STG.64
    const int ocol = col0 + q2;
    float* outN = out + (size_t)n * CONV_M * CONV_P * CONV_Q;
#pragma unroll
    for (int j = 0; j < JPT; j++) {
        int orow = row0 + rbase + j;
        if (orow < CONV_P && ocol < CONV_Q) {
#pragma unroll
            for (int m = 0; m < CONV_M; m++) {
                *reinterpret_cast<ull*>(
                    &outN[((size_t)m * CONV_P + orow) * CONV_Q + ocol]) = acc[j][m];
            }
        }
    }
}

extern "C" void kernel_launch(void* const* d_in, const int* in_sizes, int n_in,
                              void* d_out, int out_size)
{
    const float* input  = (const float*)d_in[0];   // (64,8,256,256)
    const float* filter = (const float*)d_in[1];   // (8,8,3,3)
    float* output = (float*)d_out;                 // (64,8,254,254)

    dim3 block(32, 8, 1);
    dim3 grid((CONV_Q + TILE_W - 1) / TILE_W,      // 4
              (CONV_P + TILE_H - 1) / TILE_H,      // 11
              CONV_N);                             // 64
    Im2Col_Conv2d_6854767804820_kernel<<<grid, block>>>(input, filter, output);
}

// round 5
// speedup vs baseline: 1.3310x; 1.3310x over previous
#include <cuda_runtime.h>
#include <cstdint>

// Conv2d direct: input (64,8,256,256) f32 NCHW, filter (8,8,3,3) OIHW,
// VALID, stride 1 -> out (64,8,254,254) f32.
//
// R4: fix the spill/occupancy problem. Each thread: 2 cols x 4 rows x 4 m
// (half of M) -> only 16 f32x2 accumulators (32 regs). Input rows reloaded
// per r (transient 24 regs) instead of cached across r. Target <=85 regs,
// 3 CTAs/SM (24 warps) so LDS/FFMA2 latency is actually hidden.

#define CONV_N 64
#define CONV_C 8
#define CONV_H 256
#define CONV_W 256
#define CONV_M 8
#define CONV_P 254
#define CONV_Q 254

#define TILE_W 64      // 32 threads x 2 cols
#define TILE_H 16      // 4 row-groups x 4 rows
#define JPT 4          // rows per thread
#define MH  4          // m channels per thread (half of 8)
#define CPB 4          // channels per smem pass

typedef unsigned long long ull;

__global__ __launch_bounds__(256, 3)
void Im2Col_Conv2d_6854767804820_kernel(const float* __restrict__ in,
                                        const float* __restrict__ filt,
                                        float* __restrict__ out)
{
    __shared__ float sIn[CPB][TILE_H + 2][66];                 // 4*18*66*4 = 19008 B
    __shared__ __align__(16) float2 sWd[CONV_C * 9][CONV_M];   // 72*8*8    =  4608 B

    const int tx  = threadIdx.x;            // 0..31  (column pair)
    const int ty  = threadIdx.y;            // 0..7
    const int tid = ty * 32 + tx;

    const int mh    = (ty & 1) * MH;        // m-half: 0 or 4
    const int rbase = (ty >> 1) * JPT;      // row group: 0,4,8,12

    const int col0 = blockIdx.x * TILE_W;   // 0,64,128,192
    const int row0 = blockIdx.y * TILE_H;   // 0..240
    const int n    = blockIdx.z;

    // ---- filter, duplicated pairs: sWd[rem][m] = {w, w};  rem=(c*3+r)*3+s
    for (int i = tid; i < CONV_M * CONV_C * 9; i += 256) {
        int m   = i / 72;
        int rem = i % 72;
        float w = filt[m * 72 + rem];
        sWd[rem][m] = make_float2(w, w);
    }

    const float* inN = in + (size_t)n * CONV_C * CONV_H * CONV_W;

    ull acc[JPT][MH];
#pragma unroll
    for (int j = 0; j < JPT; j++)
#pragma unroll
        for (int m = 0; m < MH; m++) acc[j][m] = 0ull;

    const int q2 = 2 * tx;
    float* sInFlat = &sIn[0][0][0];

    for (int cb = 0; cb < CONV_C / CPB; cb++) {
        __syncthreads();

        // ---- stage CPB channels of the halo tile: 4*18*66 = 4752 floats.
        // OOB rows/cols clamped to edge (those values feed only never-stored outputs).
#pragma unroll
        for (int k = 0; k < 19; k++) {
            int i = tid + k * 256;
            if (i < CPB * (TILE_H + 2) * 66) {
                int col = i % 66;
                int t   = i / 66;
                int row = t % (TILE_H + 2);
                int cl  = t / (TILE_H + 2);
                int gr = row0 + row; if (gr > CONV_H - 1) gr = CONV_H - 1;
                int gc = col0 + col; if (gc > CONV_W - 1) gc = CONV_W - 1;
                sInFlat[i] = inN[((size_t)(cb * CPB + cl) * CONV_H + gr) * CONV_W + gc];
            }
        }
        __syncthreads();

#pragma unroll
        for (int cl = 0; cl < CPB; cl++) {
            const int c = cb * CPB + cl;

#pragma unroll
            for (int r = 0; r < 3; r++) {
                // load the 4 input rows for this r as packed column pairs:
                // xa={x0,x1} xb={x2,x3} direct LDS.64; xm={x1,x2} one pack.
                ull xa[JPT], xb[JPT], xm[JPT];
#pragma unroll
                for (int j = 0; j < JPT; j++) {
                    const float* p = &sIn[cl][rbase + r + j][q2];
                    xa[j] = *reinterpret_cast<const ull*>(p);
                    xb[j] = *reinterpret_cast<const ull*>(p + 2);
                    asm("{\n\t"
                        ".reg .f32 a,b,cc,d;\n\t"
                        "mov.b64 {a,b}, %1;\n\t"
                        "mov.b64 {cc,d}, %2;\n\t"
                        "mov.b64 %0, {b,cc};\n\t"
                        "}"
                        : "=l"(xm[j]) : "l"(xa[j]), "l"(xb[j]));
                }

#pragma unroll
                for (int s = 0; s < 3; s++) {
                    // this thread's 4 duplicated weight pairs: 2x LDS.128
                    ull w2[MH];
                    const ulonglong2* wrow = reinterpret_cast<const ulonglong2*>(
                        &sWd[(c * 3 + r) * 3 + s][mh]);
#pragma unroll
                    for (int h = 0; h < MH / 2; h++) {
                        ulonglong2 v = wrow[h];
                        w2[2 * h]     = v.x;
                        w2[2 * h + 1] = v.y;
                    }

#pragma unroll
                    for (int j = 0; j < JPT; j++) {
                        ull xv = (s == 0) ? xa[j] : (s == 1) ? xm[j] : xb[j];
#pragma unroll
                        for (int m = 0; m < MH; m++) {
                            asm("fma.rn.f32x2 %0, %1, %2, %0;"
                                : "+l"(acc[j][m])
                                : "l"(xv), "l"(w2[m]));
                        }
                    }
                }
            }
        }
    }

    // ---- store: out[n][mh+m][orow][ocol], column pair via STG.64
    const int ocol = col0 + q2;
    float* outN = out + (size_t)n * CONV_M * CONV_P * CONV_Q;
    if (ocol < CONV_Q) {
#pragma unroll
        for (int j = 0; j < JPT; j++) {
            int orow = row0 + rbase + j;
            if (orow < CONV_P) {
#pragma unroll
                for (int m = 0; m < MH; m++) {
                    *reinterpret_cast<ull*>(
                        &outN[((size_t)(mh + m) * CONV_P + orow) * CONV_Q + ocol]) = acc[j][m];
                }
            }
        }
    }
}

extern "C" void kernel_launch(void* const* d_in, const int* in_sizes, int n_in,
                              void* d_out, int out_size)
{
    const float* input  = (const float*)d_in[0];   // (64,8,256,256)
    const float* filter = (const float*)d_in[1];   // (8,8,3,3)
    float* output = (float*)d_out;                 // (64,8,254,254)

    dim3 block(32, 8, 1);
    dim3 grid((CONV_Q + TILE_W - 1) / TILE_W,      // 4
              (CONV_P + TILE_H - 1) / TILE_H,      // 16
              CONV_N);                             // 64
    Im2Col_Conv2d_6854767804820_kernel<<<grid, block>>>(input, filter, output);
}

// round 6
// speedup vs baseline: 1.6046x; 1.2056x over previous
#include <cuda_runtime.h>
#include <cstdint>

// Conv2d direct: input (64,8,256,256) f32 NCHW, filter (8,8,3,3) OIHW,
// VALID, stride 1 -> out (64,8,254,254) f32.
//
// R5: same 2col x 4row x 4m f32x2 decomposition as R4 (regs=80, 3 CTAs/SM),
// but: CPB=8 with the channel loop FULLY unrolled so every LDS address is
// [Rbase + immediate] (kills the addressing ALU that was 35% of issue),
// single staging phase via cp.async float2 (LDGSTS.8), one barrier.

#define CONV_N 64
#define CONV_C 8
#define CONV_H 256
#define CONV_W 256
#define CONV_M 8
#define CONV_P 254
#define CONV_Q 254

#define TILE_W 64      // 32 threads x 2 cols
#define TILE_H 16      // 4 row-groups x 4 rows
#define JPT 4          // rows per thread
#define MH  4          // m channels per thread (half of 8)

#define ROWS_S (TILE_H + 2)   // 18
#define COLS_S 66

typedef unsigned long long ull;

__global__ __launch_bounds__(256, 3)
void Im2Col_Conv2d_6854767804820_kernel(const float* __restrict__ in,
                                        const float* __restrict__ filt,
                                        float* __restrict__ out)
{
    __shared__ float sIn[CONV_C][ROWS_S][COLS_S];              // 8*18*66*4 = 38016 B
    __shared__ __align__(16) float2 sWd[CONV_C * 9][CONV_M];   // 72*8*8    =  4608 B

    const int tx  = threadIdx.x;            // 0..31  (column pair)
    const int ty  = threadIdx.y;            // 0..7
    const int tid = ty * 32 + tx;

    const int mh    = (ty & 1) * MH;        // m-half: 0 or 4
    const int rbase = (ty >> 1) * JPT;      // row group: 0,4,8,12

    const int col0 = blockIdx.x * TILE_W;   // 0,64,128,192
    const int row0 = blockIdx.y * TILE_H;   // 0..240
    const int n    = blockIdx.z;

    const float* inN = in + (size_t)n * CONV_C * CONV_H * CONV_W;

    // ---- stage ALL 8 channels of the halo tile via cp.async (float2).
    // 8*18*33 = 4752 float2 / 256 threads -> 19 per thread (last partial).
    // OOB rows clamped to 255; OOB col-pairs clamped to start col 254. The
    // clamped values feed only outputs that the store clips (orow/ocol >= 254).
    {
        float* sInFlat = &sIn[0][0][0];
#pragma unroll
        for (int k = 0; k < 19; k++) {
            int i = tid + k * 256;
            if (i < CONV_C * ROWS_S * 33) {
                int cp  = i % 33;                 // column-pair index
                int t   = i / 33;
                int row = t % ROWS_S;
                int cl  = t / ROWS_S;
                int gr = row0 + row;     if (gr > CONV_H - 1) gr = CONV_H - 1;
                int gc = col0 + 2 * cp;  if (gc > CONV_W - 2) gc = CONV_W - 2;
                const float* src = &inN[((size_t)cl * CONV_H + gr) * CONV_W + gc];
                unsigned smem_addr =
                    (unsigned)__cvta_generic_to_shared(&sInFlat[2 * i]);
                asm volatile("cp.async.ca.shared.global [%0], [%1], 8;"
                             :: "r"(smem_addr), "l"(src));
            }
        }
        asm volatile("cp.async.commit_group;");
    }

    // ---- filter, duplicated pairs: sWd[rem][m] = {w, w};  rem=(c*3+r)*3+s
    // (runs while cp.async staging is in flight)
    for (int i = tid; i < CONV_M * CONV_C * 9; i += 256) {
        int m   = i / 72;
        int rem = i % 72;
        float w = filt[m * 72 + rem];
        sWd[rem][m] = make_float2(w, w);
    }

    ull acc[JPT][MH];
#pragma unroll
    for (int j = 0; j < JPT; j++)
#pragma unroll
        for (int m = 0; m < MH; m++) acc[j][m] = 0ull;

    const int q2 = 2 * tx;

    asm volatile("cp.async.wait_group 0;");
    __syncthreads();

    // ---- compute: fully unrolled over channel, r, s. All LDS offsets are
    // [Rbase + immediate] since cl/r/s/j are compile-time constants.
#pragma unroll
    for (int cl = 0; cl < CONV_C; cl++) {
#pragma unroll
        for (int r = 0; r < 3; r++) {
            // 4 input rows for this r as packed column pairs:
            // xa={x0,x1} xb={x2,x3} direct LDS.64; xm={x1,x2} one pack.
            ull xa[JPT], xb[JPT], xm[JPT];
#pragma unroll
            for (int j = 0; j < JPT; j++) {
                const float* p = &sIn[cl][rbase + r + j][q2];
                xa[j] = *reinterpret_cast<const ull*>(p);
                xb[j] = *reinterpret_cast<const ull*>(p + 2);
                asm("{\n\t"
                    ".reg .f32 a,b,cc,d;\n\t"
                    "mov.b64 {a,b}, %1;\n\t"
                    "mov.b64 {cc,d}, %2;\n\t"
                    "mov.b64 %0, {b,cc};\n\t"
                    "}"
                    : "=l"(xm[j]) : "l"(xa[j]), "l"(xb[j]));
            }

#pragma unroll
            for (int s = 0; s < 3; s++) {
                // this thread's 4 duplicated weight pairs: 2x LDS.128 broadcast
                ull w2[MH];
                const ulonglong2* wrow = reinterpret_cast<const ulonglong2*>(
                    &sWd[(cl * 3 + r) * 3 + s][mh]);
#pragma unroll
                for (int h = 0; h < MH / 2; h++) {
                    ulonglong2 v = wrow[h];
                    w2[2 * h]     = v.x;
                    w2[2 * h + 1] = v.y;
                }

#pragma unroll
                for (int j = 0; j < JPT; j++) {
                    ull xv = (s == 0) ? xa[j] : (s == 1) ? xm[j] : xb[j];
#pragma unroll
                    for (int m = 0; m < MH; m++) {
                        asm("fma.rn.f32x2 %0, %1, %2, %0;"
                            : "+l"(acc[j][m])
                            : "l"(xv), "l"(w2[m]));
                    }
                }
            }
        }
    }

    // ---- store: out[n][mh+m][orow][ocol], column pair via STG.64
    const int ocol = col0 + q2;
    float* outN = out + (size_t)n * CONV_M * CONV_P * CONV_Q;
    if (ocol < CONV_Q) {
#pragma unroll
        for (int j = 0; j < JPT; j++) {
            int orow = row0 + rbase + j;
            if (orow < CONV_P) {
#pragma unroll
                for (int m = 0; m < MH; m++) {
                    *reinterpret_cast<ull*>(
                        &outN[((size_t)(mh + m) * CONV_P + orow) * CONV_Q + ocol]) = acc[j][m];
                }
            }
        }
    }
}

extern "C" void kernel_launch(void* const* d_in, const int* in_sizes, int n_in,
                              void* d_out, int out_size)
{
    const float* input  = (const float*)d_in[0];   // (64,8,256,256)
    const float* filter = (const float*)d_in[1];   // (8,8,3,3)
    float* output = (float*)d_out;                 // (64,8,254,254)

    dim3 block(32, 8, 1);
    dim3 grid((CONV_Q + TILE_W - 1) / TILE_W,      // 4
              (CONV_P + TILE_H - 1) / TILE_H,      // 16
              CONV_N);                             // 64
    Im2Col_Conv2d_6854767804820_kernel<<<grid, block>>>(input, filter, output);
}